// round 8
// baseline (speedup 1.0000x reference)
#include <cuda_runtime.h>
#include <math.h>
#include <stdint.h>

#define NROWS 65536   // B*S = 8*8192
#define EDIM  256
#define NQ    8
#define FDIM  264     // NQ + EDIM

// scratch for quantum layer outputs z[row][q]
__device__ float g_z[(size_t)NROWS * NQ];

// ---------------------------------------------------------------------------
// Kernel A: z = circuit_expvals(x @ W1^T + b1 + qw)
// One warp processes 4 rows (measured-best config: ~28us).
// ---------------------------------------------------------------------------
__global__ __launch_bounds__(256) void quantum_kernel(
    const float* __restrict__ x, const float* __restrict__ W1,
    const float* __restrict__ b1, const float* __restrict__ qw)
{
    int gwarp = (blockIdx.x * 256 + threadIdx.x) >> 5;
    int lane  = threadIdx.x & 31;
    int row0  = gwarp * 4;
    if (row0 >= NROWS) return;

    const float4* x4 = reinterpret_cast<const float4*>(x);
    float4 xa[4], xb[4];
#pragma unroll
    for (int r = 0; r < 4; r++) {
        const float4* rp = x4 + (size_t)(row0 + r) * (EDIM / 4);
        xa[r] = __ldg(rp + lane);
        xb[r] = __ldg(rp + 32 + lane);
    }

    float acc[4][NQ];
    const float4* w4 = reinterpret_cast<const float4*>(W1);  // [8][64] float4
#pragma unroll
    for (int q = 0; q < NQ; q++) {
        float4 wa = __ldg(w4 + q * 64 + lane);
        float4 wb = __ldg(w4 + q * 64 + 32 + lane);
#pragma unroll
        for (int r = 0; r < 4; r++) {
            float s = xa[r].x * wa.x + xa[r].y * wa.y + xa[r].z * wa.z + xa[r].w * wa.w;
            s      += xb[r].x * wb.x + xb[r].y * wb.y + xb[r].z * wb.z + xb[r].w * wb.w;
            acc[r][q] = s;
        }
    }

#pragma unroll
    for (int r = 0; r < 4; r++)
#pragma unroll
        for (int q = 0; q < NQ; q++)
#pragma unroll
            for (int off = 16; off > 0; off >>= 1)
                acc[r][q] += __shfl_xor_sync(0xffffffffu, acc[r][q], off);

    if (lane < 4) {
        int row = row0 + lane;
        float c[NQ];
#pragma unroll
        for (int q = 0; q < NQ; q++)
            c[q] = cosf(acc[lane][q] + __ldg(b1 + q) + __ldg(qw + q));
        float zv[NQ];
        float s = c[1];
#pragma unroll
        for (int i = 2; i < NQ; i++) s *= c[i];
        zv[0] = s;                       // z0 = prod_{i=1..7} c_i
        float r = c[0];
#pragma unroll
        for (int k = 1; k < NQ; k++) { r *= c[k]; zv[k] = r; }

        float4* zp = reinterpret_cast<float4*>(g_z + (size_t)row * NQ);
        zp[0] = make_float4(zv[0], zv[1], zv[2], zv[3]);
        zp[1] = make_float4(zv[4], zv[5], zv[6], zv[7]);
    }
}

// ---------------------------------------------------------------------------
// Kernel B: out[n,e] = sum_f y[n,f]*W2[e,f] + b2[e],  y = [z | x]
// tf32 mma.sync.m16n8k8, CTA 128x128, 8 warps (2x4), warp tile 64x32.
// PADK=12: conflict-free scalar fragment LDS AND 16B-aligned conflict-free
// STS.128 stores. Depth-2 register prefetch ring covers ~2 ktiles of LDG
// latency before the STS that publishes a buffer. One sync per K-iter.
// ---------------------------------------------------------------------------
#define BM 128
#define BN 128
#define BK 8
#define PADK 12
#define KTILES (FDIM / BK)   // 33

// tf32 is a b32-typed value in PTX: destination must be a .b32 register.
__device__ __forceinline__ uint32_t to_tf32(float v) {
    uint32_t r;
    asm("cvt.rna.tf32.f32 %0, %1;" : "=r"(r) : "f"(v));
    return r;
}
__device__ __forceinline__ float to_tf32f(float v) {
    return __uint_as_float(to_tf32(v));
}
__device__ __forceinline__ float4 cvt4(float4 v) {
    return make_float4(to_tf32f(v.x), to_tf32f(v.y), to_tf32f(v.z), to_tf32f(v.w));
}

__device__ __forceinline__ void mma_tf32(float* d, const uint32_t* a, const uint32_t* b) {
    asm volatile(
        "mma.sync.aligned.m16n8k8.row.col.f32.tf32.tf32.f32 "
        "{%0,%1,%2,%3},{%4,%5,%6,%7},{%8,%9},{%0,%1,%2,%3};"
        : "+f"(d[0]), "+f"(d[1]), "+f"(d[2]), "+f"(d[3])
        : "r"(a[0]), "r"(a[1]), "r"(a[2]), "r"(a[3]), "r"(b[0]), "r"(b[1]));
}

__global__ __launch_bounds__(256, 2) void gemm_kernel(
    const float* __restrict__ x, const float* __restrict__ W2,
    const float* __restrict__ b2, float* __restrict__ out)
{
    __shared__ __align__(16) float As[2][BM][PADK];   // [row m][k]
    __shared__ __align__(16) float Bs[2][BN][PADK];   // [col n][k]

    int tid  = threadIdx.x;
    int wid  = tid >> 5;
    int lane = tid & 31;
    int g    = lane >> 2;   // 0..7
    int q    = lane & 3;    // 0..3

    int warp_m = (wid & 1) * 64;   // 0 or 64
    int warp_n = (wid >> 1) * 32;  // 0,32,64,96

    int rowBase = blockIdx.x * BM;
    int colBase = blockIdx.y * BN;

    // loader mapping: 256 threads, one float4 each for A and B per K-tile
    int lr = tid >> 1;          // 0..127
    int lc = (tid & 1) * 4;     // 0 or 4

    const float* Az = g_z + (size_t)(rowBase + lr) * NQ + lc;
    const float* Ax = x   + (size_t)(rowBase + lr) * EDIM + lc;
    const float* Bw = W2  + (size_t)(colBase + lr) * FDIM + lc;

    float acc[4][4][4];
#pragma unroll
    for (int i = 0; i < 4; i++)
#pragma unroll
        for (int j = 0; j < 4; j++)
#pragma unroll
            for (int v = 0; v < 4; v++) acc[i][j][v] = 0.f;

    // prologue: tile 0 (the z tile) into buffer 0
    {
        float4 av = cvt4(*reinterpret_cast<const float4*>(Az));
        float4 bv = cvt4(*reinterpret_cast<const float4*>(Bw));
        *reinterpret_cast<float4*>(&As[0][lr][lc]) = av;
        *reinterpret_cast<float4*>(&Bs[0][lr][lc]) = bv;
    }
    // prefetch ring: set p holds tile T issued ~2 iters before its STS.
    float4 pa[2], pb[2];
    pa[1] = *reinterpret_cast<const float4*>(Ax);            // tile 1 = x block 0
    pb[1] = *reinterpret_cast<const float4*>(Bw + BK);       // tile 1
    __syncthreads();

    for (int kt = 0; kt < KTILES; kt++) {
        int cur = kt & 1;
        int nxt = cur ^ 1;

        // issue LDG for tile kt+2 into the set just freed last iteration
        if (kt + 2 < KTILES) {
            pa[cur] = *reinterpret_cast<const float4*>(Ax + (kt + 1) * BK);
            pb[cur] = *reinterpret_cast<const float4*>(Bw + (kt + 2) * BK);
        }

        // fragment loads (conflict-free via PADK=12)
        uint32_t afr[4][4], bfr[4][2];
#pragma unroll
        for (int ma = 0; ma < 4; ma++) {
            int r0 = warp_m + ma * 16 + g;
            afr[ma][0] = __float_as_uint(As[cur][r0    ][q    ]);
            afr[ma][1] = __float_as_uint(As[cur][r0 + 8][q    ]);
            afr[ma][2] = __float_as_uint(As[cur][r0    ][q + 4]);
            afr[ma][3] = __float_as_uint(As[cur][r0 + 8][q + 4]);
        }
#pragma unroll
        for (int nb = 0; nb < 4; nb++) {
            int c0 = warp_n + nb * 8 + g;
            bfr[nb][0] = __float_as_uint(Bs[cur][c0][q    ]);
            bfr[nb][1] = __float_as_uint(Bs[cur][c0][q + 4]);
        }

#pragma unroll
        for (int ma = 0; ma < 4; ma++)
#pragma unroll
            for (int nb = 0; nb < 4; nb++)
                mma_tf32(acc[ma][nb], afr[ma], bfr[nb]);

        // publish tile kt+1 (held in set nxt, issued ~2 iters ago)
        if (kt + 1 < KTILES) {
            *reinterpret_cast<float4*>(&As[nxt][lr][lc]) = cvt4(pa[nxt]);
            *reinterpret_cast<float4*>(&Bs[nxt][lr][lc]) = cvt4(pb[nxt]);
            __syncthreads();
        }
    }

    // epilogue: bias + store. c0,c1 at (g, 2q..2q+1); c2,c3 at (g+8, ...)
#pragma unroll
    for (int ma = 0; ma < 4; ma++) {
#pragma unroll
        for (int nb = 0; nb < 4; nb++) {
            int col  = colBase + warp_n + nb * 8 + 2 * q;
            int row0 = rowBase + warp_m + ma * 16 + g;
            float bias0 = __ldg(b2 + col);
            float bias1 = __ldg(b2 + col + 1);
            float2 v0 = make_float2(acc[ma][nb][0] + bias0, acc[ma][nb][1] + bias1);
            float2 v1 = make_float2(acc[ma][nb][2] + bias0, acc[ma][nb][3] + bias1);
            *reinterpret_cast<float2*>(out + (size_t)row0 * EDIM + col)       = v0;
            *reinterpret_cast<float2*>(out + (size_t)(row0 + 8) * EDIM + col) = v1;
        }
    }
}

// ---------------------------------------------------------------------------
extern "C" void kernel_launch(void* const* d_in, const int* in_sizes, int n_in,
                              void* d_out, int out_size) {
    const float* x  = (const float*)d_in[0];
    const float* W1 = (const float*)d_in[1];
    const float* b1 = (const float*)d_in[2];
    const float* qw = (const float*)d_in[3];
    const float* W2 = (const float*)d_in[4];
    const float* b2 = (const float*)d_in[5];
    float* out = (float*)d_out;

    // Kernel A: 8 warps/block * 4 rows/warp = 32 rows per block
    quantum_kernel<<<NROWS / 32, 256>>>(x, W1, b1, qw);

    dim3 grid(NROWS / BM, EDIM / BN);
    gemm_kernel<<<grid, 256>>>(x, W2, b2, out);
}

// round 9
// speedup vs baseline: 1.2986x; 1.2986x over previous
#include <cuda_runtime.h>
#include <math.h>
#include <stdint.h>

#define NROWS 65536   // B*S = 8*8192
#define EDIM  256
#define NQ    8
#define FDIM  264     // NQ + EDIM

// scratch for quantum layer outputs z[row][q]
__device__ float g_z[(size_t)NROWS * NQ];

// ---------------------------------------------------------------------------
// Kernel A: z = circuit_expvals(x @ W1^T + b1 + qw)
// One warp processes 4 rows (measured-best config: ~28us).
// ---------------------------------------------------------------------------
__global__ __launch_bounds__(256) void quantum_kernel(
    const float* __restrict__ x, const float* __restrict__ W1,
    const float* __restrict__ b1, const float* __restrict__ qw)
{
    int gwarp = (blockIdx.x * 256 + threadIdx.x) >> 5;
    int lane  = threadIdx.x & 31;
    int row0  = gwarp * 4;
    if (row0 >= NROWS) return;

    const float4* x4 = reinterpret_cast<const float4*>(x);
    float4 xa[4], xb[4];
#pragma unroll
    for (int r = 0; r < 4; r++) {
        const float4* rp = x4 + (size_t)(row0 + r) * (EDIM / 4);
        xa[r] = __ldg(rp + lane);
        xb[r] = __ldg(rp + 32 + lane);
    }

    float acc[4][NQ];
    const float4* w4 = reinterpret_cast<const float4*>(W1);  // [8][64] float4
#pragma unroll
    for (int q = 0; q < NQ; q++) {
        float4 wa = __ldg(w4 + q * 64 + lane);
        float4 wb = __ldg(w4 + q * 64 + 32 + lane);
#pragma unroll
        for (int r = 0; r < 4; r++) {
            float s = xa[r].x * wa.x + xa[r].y * wa.y + xa[r].z * wa.z + xa[r].w * wa.w;
            s      += xb[r].x * wb.x + xb[r].y * wb.y + xb[r].z * wb.z + xb[r].w * wb.w;
            acc[r][q] = s;
        }
    }

#pragma unroll
    for (int r = 0; r < 4; r++)
#pragma unroll
        for (int q = 0; q < NQ; q++)
#pragma unroll
            for (int off = 16; off > 0; off >>= 1)
                acc[r][q] += __shfl_xor_sync(0xffffffffu, acc[r][q], off);

    if (lane < 4) {
        int row = row0 + lane;
        float c[NQ];
#pragma unroll
        for (int q = 0; q < NQ; q++)
            c[q] = cosf(acc[lane][q] + __ldg(b1 + q) + __ldg(qw + q));
        float zv[NQ];
        float s = c[1];
#pragma unroll
        for (int i = 2; i < NQ; i++) s *= c[i];
        zv[0] = s;                       // z0 = prod_{i=1..7} c_i
        float r = c[0];
#pragma unroll
        for (int k = 1; k < NQ; k++) { r *= c[k]; zv[k] = r; }

        float4* zp = reinterpret_cast<float4*>(g_z + (size_t)row * NQ);
        zp[0] = make_float4(zv[0], zv[1], zv[2], zv[3]);
        zp[1] = make_float4(zv[4], zv[5], zv[6], zv[7]);
    }
}

// ---------------------------------------------------------------------------
// Kernel B: out[n,e] = sum_f y[n,f]*W2[e,f] + b2[e],  y = [z | x]
// tf32 mma.sync.m16n8k8, CTA 128x128, 8 warps (2x4), warp tile 64x32.
// BK=16 pipeline stages built from TWO proven BK=8 / PADK=12 sub-tiles:
// fragment indexing, bank-conflict layout and STS.128 alignment unchanged.
// 17 barriers total (vs 33); 32 MMAs of compute per sync window.
// Scalar prefetch registers only (no dynamically-indexed register arrays —
// that was the Round-8 regression).
// F blocks of 8: block 0 = z, blocks 1..32 = x blocks 0..31.
// Pre-stage computes block 0; stage s (1..16) computes blocks 2s-1, 2s.
// ---------------------------------------------------------------------------
#define BM 128
#define BN 128
#define BK 8
#define PADK 12

// tf32 is a b32-typed value in PTX: destination must be a .b32 register.
__device__ __forceinline__ uint32_t to_tf32(float v) {
    uint32_t r;
    asm("cvt.rna.tf32.f32 %0, %1;" : "=r"(r) : "f"(v));
    return r;
}
__device__ __forceinline__ float to_tf32f(float v) {
    return __uint_as_float(to_tf32(v));
}
__device__ __forceinline__ float4 cvt4(float4 v) {
    return make_float4(to_tf32f(v.x), to_tf32f(v.y), to_tf32f(v.z), to_tf32f(v.w));
}

__device__ __forceinline__ void mma_tf32(float* d, const uint32_t* a, const uint32_t* b) {
    asm volatile(
        "mma.sync.aligned.m16n8k8.row.col.f32.tf32.tf32.f32 "
        "{%0,%1,%2,%3},{%4,%5,%6,%7},{%8,%9},{%0,%1,%2,%3};"
        : "+f"(d[0]), "+f"(d[1]), "+f"(d[2]), "+f"(d[3])
        : "r"(a[0]), "r"(a[1]), "r"(a[2]), "r"(a[3]), "r"(b[0]), "r"(b[1]));
}

__global__ __launch_bounds__(256, 2) void gemm_kernel(
    const float* __restrict__ x, const float* __restrict__ W2,
    const float* __restrict__ b2, float* __restrict__ out)
{
    // [stage][sub][row][k] — 48 KB total (A+B)
    __shared__ __align__(16) float As[2][2][BM][PADK];
    __shared__ __align__(16) float Bs[2][2][BN][PADK];

    int tid  = threadIdx.x;
    int wid  = tid >> 5;
    int lane = tid & 31;
    int g    = lane >> 2;   // 0..7
    int q    = lane & 3;    // 0..3

    int warp_m = (wid & 1) * 64;   // 0 or 64
    int warp_n = (wid >> 1) * 32;  // 0,32,64,96

    int rowBase = blockIdx.x * BM;
    int colBase = blockIdx.y * BN;

    // loader mapping (per sub-tile): 256 threads, one float4 each
    int lr = tid >> 1;          // 0..127
    int lc = (tid & 1) * 4;     // 0 or 4

    const float* Az = g_z + (size_t)(rowBase + lr) * NQ + lc;
    const float* Ax = x   + (size_t)(rowBase + lr) * EDIM + lc;
    const float* Bw = W2  + (size_t)(colBase + lr) * FDIM + lc;

    float acc[4][4][4];
#pragma unroll
    for (int i = 0; i < 4; i++)
#pragma unroll
        for (int j = 0; j < 4; j++)
#pragma unroll
            for (int v = 0; v < 4; v++) acc[i][j][v] = 0.f;

    // ---- pre-stage: F block 0 (z) into stage 0 / sub 0 ----
    {
        float4 av = cvt4(*reinterpret_cast<const float4*>(Az));
        float4 bv = cvt4(*reinterpret_cast<const float4*>(Bw));
        *reinterpret_cast<float4*>(&As[0][0][lr][lc]) = av;
        *reinterpret_cast<float4*>(&Bs[0][0][lr][lc]) = bv;
    }
    // prefetch stage 1 = F blocks 1,2 (x blocks 0,1; W2 blocks 1,2)
    float4 pa0 = *reinterpret_cast<const float4*>(Ax);
    float4 pa1 = *reinterpret_cast<const float4*>(Ax + BK);
    float4 pb0 = *reinterpret_cast<const float4*>(Bw + BK);
    float4 pb1 = *reinterpret_cast<const float4*>(Bw + 2 * BK);
    __syncthreads();

    // compute pre-stage (sub 0 only)
    {
        uint32_t afr[4][4], bfr[4][2];
#pragma unroll
        for (int ma = 0; ma < 4; ma++) {
            int r0 = warp_m + ma * 16 + g;
            afr[ma][0] = __float_as_uint(As[0][0][r0    ][q    ]);
            afr[ma][1] = __float_as_uint(As[0][0][r0 + 8][q    ]);
            afr[ma][2] = __float_as_uint(As[0][0][r0    ][q + 4]);
            afr[ma][3] = __float_as_uint(As[0][0][r0 + 8][q + 4]);
        }
#pragma unroll
        for (int nb = 0; nb < 4; nb++) {
            int c0 = warp_n + nb * 8 + g;
            bfr[nb][0] = __float_as_uint(Bs[0][0][c0][q    ]);
            bfr[nb][1] = __float_as_uint(Bs[0][0][c0][q + 4]);
        }
#pragma unroll
        for (int ma = 0; ma < 4; ma++)
#pragma unroll
            for (int nb = 0; nb < 4; nb++)
                mma_tf32(acc[ma][nb], afr[ma], bfr[nb]);
    }
    // publish stage 1
    *reinterpret_cast<float4*>(&As[1][0][lr][lc]) = cvt4(pa0);
    *reinterpret_cast<float4*>(&As[1][1][lr][lc]) = cvt4(pa1);
    *reinterpret_cast<float4*>(&Bs[1][0][lr][lc]) = cvt4(pb0);
    *reinterpret_cast<float4*>(&Bs[1][1][lr][lc]) = cvt4(pb1);
    __syncthreads();

    // ---- main loop: stages 1..16, each = F blocks 2s-1, 2s ----
    for (int s = 1; s <= 16; s++) {
        int cur = s & 1;
        int nxt = cur ^ 1;
        bool has_next = (s < 16);

        // prefetch stage s+1 = F blocks 2s+1, 2s+2 (x blocks 2s, 2s+1)
        if (has_next) {
            pa0 = *reinterpret_cast<const float4*>(Ax + (2 * s    ) * BK);
            pa1 = *reinterpret_cast<const float4*>(Ax + (2 * s + 1) * BK);
            pb0 = *reinterpret_cast<const float4*>(Bw + (2 * s + 1) * BK);
            pb1 = *reinterpret_cast<const float4*>(Bw + (2 * s + 2) * BK);
        }

#pragma unroll
        for (int sub = 0; sub < 2; sub++) {
            uint32_t afr[4][4], bfr[4][2];
#pragma unroll
            for (int ma = 0; ma < 4; ma++) {
                int r0 = warp_m + ma * 16 + g;
                afr[ma][0] = __float_as_uint(As[cur][sub][r0    ][q    ]);
                afr[ma][1] = __float_as_uint(As[cur][sub][r0 + 8][q    ]);
                afr[ma][2] = __float_as_uint(As[cur][sub][r0    ][q + 4]);
                afr[ma][3] = __float_as_uint(As[cur][sub][r0 + 8][q + 4]);
            }
#pragma unroll
            for (int nb = 0; nb < 4; nb++) {
                int c0 = warp_n + nb * 8 + g;
                bfr[nb][0] = __float_as_uint(Bs[cur][sub][c0][q    ]);
                bfr[nb][1] = __float_as_uint(Bs[cur][sub][c0][q + 4]);
            }
#pragma unroll
            for (int ma = 0; ma < 4; ma++)
#pragma unroll
                for (int nb = 0; nb < 4; nb++)
                    mma_tf32(acc[ma][nb], afr[ma], bfr[nb]);
        }

        if (has_next) {
            *reinterpret_cast<float4*>(&As[nxt][0][lr][lc]) = cvt4(pa0);
            *reinterpret_cast<float4*>(&As[nxt][1][lr][lc]) = cvt4(pa1);
            *reinterpret_cast<float4*>(&Bs[nxt][0][lr][lc]) = cvt4(pb0);
            *reinterpret_cast<float4*>(&Bs[nxt][1][lr][lc]) = cvt4(pb1);
            __syncthreads();
        }
    }

    // epilogue: bias + store. c0,c1 at (g, 2q..2q+1); c2,c3 at (g+8, ...)
#pragma unroll
    for (int ma = 0; ma < 4; ma++) {
#pragma unroll
        for (int nb = 0; nb < 4; nb++) {
            int col  = colBase + warp_n + nb * 8 + 2 * q;
            int row0 = rowBase + warp_m + ma * 16 + g;
            float bias0 = __ldg(b2 + col);
            float bias1 = __ldg(b2 + col + 1);
            float2 v0 = make_float2(acc[ma][nb][0] + bias0, acc[ma][nb][1] + bias1);
            float2 v1 = make_float2(acc[ma][nb][2] + bias0, acc[ma][nb][3] + bias1);
            *reinterpret_cast<float2*>(out + (size_t)row0 * EDIM + col)       = v0;
            *reinterpret_cast<float2*>(out + (size_t)(row0 + 8) * EDIM + col) = v1;
        }
    }
}

// ---------------------------------------------------------------------------
extern "C" void kernel_launch(void* const* d_in, const int* in_sizes, int n_in,
                              void* d_out, int out_size) {
    const float* x  = (const float*)d_in[0];
    const float* W1 = (const float*)d_in[1];
    const float* b1 = (const float*)d_in[2];
    const float* qw = (const float*)d_in[3];
    const float* W2 = (const float*)d_in[4];
    const float* b2 = (const float*)d_in[5];
    float* out = (float*)d_out;

    // Kernel A: 8 warps/block * 4 rows/warp = 32 rows per block
    quantum_kernel<<<NROWS / 32, 256>>>(x, W1, b1, qw);

    dim3 grid(NROWS / BM, EDIM / BN);
    gemm_kernel<<<grid, 256>>>(x, W2, b2, out);
}